// round 13
// baseline (speedup 1.0000x reference)
#include <cuda_runtime.h>
#include <cuda_fp16.h>
#include <cstdint>

// Problem constants
#define BB 4
#define CC 3
#define HH 384
#define WW 384
#define KK 5
#define K2 25
#define HWSZ (HH * WW)          // 147456
#define NUM_ITER 20
#define INVZ2 44.4444444444444444f   // 1 / 0.15^2

// ---------------- precompute tile ----------------
#define PTX 32
#define PTY 16
#define PLX (PTX + 4)
#define PLY (PTY + 4)

// ---------------- persistent kernel geometry (R12-proven) ----------------
// 288 blocks (6 x 12 x 4), 512 threads (32 x 16), each thread owns a 2x2
// pixel quad -> tile = 64 x 32 pixels. 2 blocks/SM x 148 SMs = 296 >= 288,
// so ALL blocks are co-resident and software barriers are safe.
#define TILE_W 64
#define TILE_H 32
#define XS_W (TILE_W + 4)    // 68
#define XS_H (TILE_H + 4)    // 36
#define NQ 512
#define GRID_X (WW / TILE_W) // 6
#define GRID_Y (HH / TILE_H) // 12
#define NROWCNT (BB * GRID_Y)        // 48 row counters

#define SMEM_W_BYTES (K2 * NQ * 8)                       // 102400
#define SMEM_X_BYTES (XS_H * XS_W * 4)                   // 9792
#define SMEM_DYN (SMEM_W_BYTES + SMEM_X_BYTES + 16)      // pad for tail reads

// Scratch (global):
__device__ __half    g_wp[(size_t)BB * K2 * HWSZ];   // fp16 normalized weights
__device__ float     g_c [(size_t)BB * HWSZ];        // mask / sum(quantized w)
__device__ float     g_x[2][(size_t)BB * HWSZ];      // ping-pong border exchange
__device__ unsigned  g_count[NROWCNT];               // per-block-row counters

// ---------------------------------------------------------------------------
// Kernel 1: normalized bilateral weights -> fp16 planes, fp32 renorm factor
// c = mask / sum(dequantized fp16 weights), x0 = feat * mask, counter reset.
// img shifted by +10 BEFORE zero padding (matches reference): OOB taps use
// padded value 0 and their affinity underflows to exactly 0.
// ---------------------------------------------------------------------------
__global__ void __launch_bounds__(512) precompute_kernel(
    const float* __restrict__ img,
    const float* __restrict__ feat,
    const float* __restrict__ mask)
{
    if (blockIdx.x == 0 && blockIdx.y == 0 && blockIdx.z == 0 &&
        threadIdx.y == 0 && threadIdx.x < NROWCNT)
        g_count[threadIdx.x] = 0u;

    __shared__ float s[PLY][PLX][CC];

    const int b  = blockIdx.z;
    const int h0 = blockIdx.y * PTY;
    const int w0 = blockIdx.x * PTX;
    const int tx = threadIdx.x, ty = threadIdx.y;
    const int tid = ty * PTX + tx;

    const float* imb = img + (size_t)b * CC * HWSZ;

    for (int i = tid; i < PLY * PLX; i += PTX * PTY) {
        int ly = i / PLX, lx = i - ly * PLX;
        int gh = h0 + ly - 2, gw = w0 + lx - 2;
        bool ok = (gh >= 0) && (gh < HH) && (gw >= 0) && (gw < WW);
        #pragma unroll
        for (int c = 0; c < CC; c++)
            s[ly][lx][c] = ok ? imb[(size_t)c * HWSZ + gh * WW + gw] + 10.0f : 0.0f;
    }
    __syncthreads();

    const float c0 = s[ty + 2][tx + 2][0];
    const float c1 = s[ty + 2][tx + 2][1];
    const float c2 = s[ty + 2][tx + 2][2];

    float aff[K2];
    float sum = 0.0f;
    #pragma unroll
    for (int k = 0; k < K2; k++) {
        const int dy = k / KK, dx = k % KK;
        float d0 = s[ty + dy][tx + dx][0] - c0;
        float d1 = s[ty + dy][tx + dx][1] - c1;
        float d2 = s[ty + dy][tx + dx][2] - c2;
        float d  = d0 * d0 + d1 * d1 + d2 * d2;
        float a  = __expf(-d * INVZ2);
        aff[k] = a;
        sum += a;
    }
    const float inv = 1.0f / (sum + 1e-10f);

    __half q[K2];
    float qs = 0.0f;
    #pragma unroll
    for (int k = 0; k < K2; k++) {
        q[k] = __float2half_rn(aff[k] * inv);
        qs += __half2float(q[k]);
    }

    const int gh = h0 + ty, gw = w0 + tx;
    const size_t pix = (size_t)gh * WW + gw;
    const size_t p = (size_t)b * HWSZ + pix;

    __half* wb = g_wp + (size_t)b * K2 * HWSZ + pix;
    #pragma unroll
    for (int k = 0; k < K2; k++)
        wb[(size_t)k * HWSZ] = q[k];

    const float mk = mask[p];
    g_c[p] = mk / qs;
    g_x[0][p] = feat[p] * mk;
}

// ---------------------------------------------------------------------------
// Kernel 2: persistent — all 20 iterations, per-block-row counters:
// arrive at own row's counter; wait only on rows by-1, by, by+1 (the only
// rows this block's halo touches). Same fence-fence + atomic-RMW protocol
// as the proven batch barrier, but the wait set is 18 blocks, not 72.
// ---------------------------------------------------------------------------
__global__ void __launch_bounds__(512, 2) persist_kernel(
    float* __restrict__ out)
{
    extern __shared__ char smem_raw[];
    uint2* ws = reinterpret_cast<uint2*>(smem_raw);                   // [25][NQ]
    float* xs = reinterpret_cast<float*>(smem_raw + SMEM_W_BYTES);    // [XS_H][XS_W]

    const int tx = threadIdx.x, ty = threadIdx.y;
    const int tid = ty * 32 + tx;
    const int quad = tid;

    const int b  = blockIdx.z;
    const int by = blockIdx.y;
    const int h0 = by * TILE_H;
    const int w0 = blockIdx.x * TILE_W;

    const int r0 = 2 * ty;          // local px rows r0, r0+1
    const int c0 = 2 * tx;          // local px cols c0, c0+1
    const size_t p00 = (size_t)(h0 + r0)     * WW + (w0 + c0);
    const size_t p10 = (size_t)(h0 + r0 + 1) * WW + (w0 + c0);

    // row counters: own + up to 2 adjacent rows; lane `tid` polls pollrow[tid]
    unsigned* mycnt = &g_count[b * GRID_Y + by];
    int pollrow = -1;
    if (tid == 0) pollrow = by;
    else if (tid == 1 && by > 0)          pollrow = by - 1;
    else if (tid == 2 && by < GRID_Y - 1) pollrow = by + 1;
    unsigned* pollcnt = (pollrow >= 0) ? &g_count[b * GRID_Y + pollrow] : nullptr;

    // ---- one-time: weights -> smem (uint2 = {half2 row0, half2 row1}) ----
    const __half* wp = g_wp + (size_t)b * K2 * HWSZ;
    #pragma unroll
    for (int k = 0; k < K2; k++) {
        unsigned lo = *reinterpret_cast<const unsigned*>(wp + (size_t)k * HWSZ + p00);
        unsigned hi = *reinterpret_cast<const unsigned*>(wp + (size_t)k * HWSZ + p10);
        ws[k * NQ + quad] = make_uint2(lo, hi);
    }

    // renorm factors (mask folded) — register resident
    const float* cb = g_c + (size_t)b * HWSZ;
    const float2 cf0 = *reinterpret_cast<const float2*>(cb + p00);
    const float2 cf1 = *reinterpret_cast<const float2*>(cb + p10);

    // ---- one-time: interior x -> smem ----
    {
        const float* x0g = &g_x[0][(size_t)b * HWSZ];
        float2 i0 = *reinterpret_cast<const float2*>(x0g + p00);
        float2 i1 = *reinterpret_cast<const float2*>(x0g + p10);
        *reinterpret_cast<float2*>(&xs[(r0 + 2) * XS_W + c0 + 2]) = i0;
        *reinterpret_cast<float2*>(&xs[(r0 + 3) * XS_W + c0 + 2]) = i1;
    }

    // direct ring mapping (tid < 400)
    int rly = -1, rlx = 0;
    if (tid < 136)        { rly = tid / 68;            rlx = tid % 68; }
    else if (tid < 272)   { int t = tid - 136; rly = 34 + t / 68; rlx = t % 68; }
    else if (tid < 336)   { int t = tid - 272; rlx = t & 1;       rly = 2 + (t >> 1); }
    else if (tid < 400)   { int t = tid - 336; rlx = 66 + (t & 1); rly = 2 + (t >> 1); }
    int rgh = 0, rgw = 0; bool rok = false;
    if (rly >= 0) {
        rgh = h0 + rly - 2; rgw = w0 + rlx - 2;
        rok = (rgh >= 0) && (rgh < HH) && (rgw >= 0) && (rgw < WW);
    }

    const bool b0row = (r0 < 2) || (r0 >= TILE_H - 2);
    const bool b1row = (r0 + 1 < 2) || (r0 + 1 >= TILE_H - 2);
    const bool bcol  = (c0 < 2) || (c0 + 1 >= TILE_W - 2);
    const bool pub0 = b0row || bcol;
    const bool pub1 = b1row || bcol;

    for (int it = 0; it < NUM_ITER; it++) {
        // ---- halo ring from global (neighbors' previous-iter borders) ----
        if (rly >= 0) {
            const float* src = &g_x[it & 1][(size_t)b * HWSZ];
            float v = 0.0f;
            if (rok) v = __ldcg(src + (size_t)rgh * WW + rgw);
            xs[rly * XS_W + rlx] = v;
        }
        __syncthreads();   // covers one-time init at it=0 as well

        // ---- compute 2x2 quad ----
        float a00 = 0.f, a01 = 0.f, a10 = 0.f, a11 = 0.f;
        uint2 Wp[5];
        #pragma unroll
        for (int j = 0; j < 6; j++) {
            const float* row = &xs[(r0 + j) * XS_W + c0];
            float2 va = *reinterpret_cast<const float2*>(row);
            float2 vb = *reinterpret_cast<const float2*>(row + 2);
            float2 vc = *reinterpret_cast<const float2*>(row + 4);
            float2 vd = *reinterpret_cast<const float2*>(row + 6);
            float v[7] = { va.x, va.y, vb.x, vb.y, vc.x, vc.y, vd.x };

            uint2 Wc[5];
            if (j < 5) {
                #pragma unroll
                for (int dx = 0; dx < 5; dx++)
                    Wc[dx] = ws[(j * 5 + dx) * NQ + quad];
            }
            #pragma unroll
            for (int dx = 0; dx < 5; dx++) {
                if (j < 5) {
                    float2 fA = __half22float2(*reinterpret_cast<__half2*>(&Wc[dx].x));
                    a00 = fmaf(fA.x, v[dx], a00);
                    a01 = fmaf(fA.y, v[dx + 1], a01);
                }
                if (j >= 1) {
                    float2 fB = __half22float2(*reinterpret_cast<__half2*>(&Wp[dx].y));
                    a10 = fmaf(fB.x, v[dx], a10);
                    a11 = fmaf(fB.y, v[dx + 1], a11);
                }
            }
            if (j < 5) {
                #pragma unroll
                for (int dx = 0; dx < 5; dx++) Wp[dx] = Wc[dx];
            }
        }

        const float o00 = a00 * cf0.x, o01 = a01 * cf0.y;
        const float o10 = a10 * cf1.x, o11 = a11 * cf1.y;

        __syncthreads();   // all reads of xs done before any overwrite

        if (it == NUM_ITER - 1) {
            // final: write full frame to out, no barrier needed
            float* ob = out + (size_t)b * HWSZ;
            *reinterpret_cast<float2*>(ob + p00) = make_float2(o00, o01);
            *reinterpret_cast<float2*>(ob + p10) = make_float2(o10, o11);
        } else {
            // publish my 2-wide border for neighbors' next-iter halo
            float* dst = &g_x[(it + 1) & 1][(size_t)b * HWSZ];
            if (pub0) *reinterpret_cast<float2*>(dst + p00) = make_float2(o00, o01);
            if (pub1) *reinterpret_cast<float2*>(dst + p10) = make_float2(o10, o11);

            __threadfence();     // border writes globally visible (quiescent)
            __syncthreads();     // all threads' writes fenced before arrival

            // ---- arrive at own row counter ----
            if (tid == 0)
                atomicAdd(mycnt, 1u);

            // overlap the spin window: write next-iter interior to smem now
            *reinterpret_cast<float2*>(&xs[(r0 + 2) * XS_W + c0 + 2]) = make_float2(o00, o01);
            *reinterpret_cast<float2*>(&xs[(r0 + 3) * XS_W + c0 + 2]) = make_float2(o10, o11);

            // ---- wait: rows by-1, by, by+1 complete (lanes 0-2 parallel) ----
            if (pollcnt) {
                const unsigned target = (unsigned)(it + 1) * GRID_X;
                while (*(volatile unsigned*)pollcnt < target) { }
                __threadfence();
            }
            __syncthreads();
        }
    }
}

// ---------------------------------------------------------------------------
extern "C" void kernel_launch(void* const* d_in, const int* in_sizes, int n_in,
                              void* d_out, int out_size)
{
    const float* img  = (const float*)d_in[0];
    const float* feat = (const float*)d_in[1];
    const float* mask = (const float*)d_in[2];
    float* out = (float*)d_out;

    cudaFuncSetAttribute(persist_kernel,
                         cudaFuncAttributeMaxDynamicSharedMemorySize, SMEM_DYN);

    dim3 pblk(PTX, PTY);
    dim3 pgrd(WW / PTX, HH / PTY, BB);    // (12, 24, 4)
    precompute_kernel<<<pgrd, pblk>>>(img, feat, mask);

    dim3 iblk(32, 16);
    dim3 igrd(GRID_X, GRID_Y, BB);        // (6, 12, 4) = 288 blocks
    persist_kernel<<<igrd, iblk, SMEM_DYN>>>(out);
}

// round 14
// speedup vs baseline: 1.0169x; 1.0169x over previous
#include <cuda_runtime.h>
#include <cuda_fp16.h>
#include <cstdint>

// Problem constants
#define BB 4
#define CC 3
#define HH 384
#define WW 384
#define KK 5
#define K2 25
#define HWSZ (HH * WW)          // 147456
#define NUM_ITER 20
#define INVZ2 44.4444444444444444f   // 1 / 0.15^2

// ---------------- persistent kernel geometry (R12-proven) ----------------
// 288 blocks (6 x 12 x 4), 512 threads (32 x 16), each thread owns a 2x2
// pixel quad -> tile = 64 x 32 pixels. 2 blocks/SM x 148 SMs = 296 >= 288,
// so ALL blocks are co-resident and software barriers are safe.
#define TILE_W 64
#define TILE_H 32
#define XS_W (TILE_W + 4)    // 68
#define XS_H (TILE_H + 4)    // 36
#define NQ 512
#define GRID_X (WW / TILE_W) // 6
#define GRID_Y (HH / TILE_H) // 12
#define NBLK_B (GRID_X * GRID_Y)     // 72 blocks per batch

// SMEM layout:
//  [0, 102400)        ws: fp16 weights, uint2 [25][NQ] (tap k at k*4096)
//  [102400, 112192)   xs: x tile [36][68] fp32
//  [112192, 112208)   pad (vd float2 tail overread on last xs row)
//  Staging (init only): img 3ch tile [3][36][68] fp32 = 29376 B at
//  [82832, 112208) — overlaps ws taps 20..24 + xs. Taps 0..19 are written
//  during generation (region [0, 81920) — disjoint); taps 20..24 are kept
//  in registers and stored after the staging-read sync. xs is written after
//  generation as well.
#define SMEM_W_BYTES (K2 * NQ * 8)                       // 102400
#define SMEM_X_BYTES (XS_H * XS_W * 4)                   // 9792
#define SMEM_DYN (SMEM_W_BYTES + SMEM_X_BYTES + 16)      // 112208
#define STG_BYTES (CC * XS_H * XS_W * 4)                 // 29376
#define STG_OFF (SMEM_DYN - STG_BYTES)                   // 82832 (16B aligned)
#define DEFER_K 20                                       // taps >= 20 deferred

// Scratch (global):
__device__ float     g_x[2][(size_t)BB * HWSZ];      // ping-pong border exchange
__device__ unsigned  g_count[BB];                    // per-batch barrier counters
__device__ unsigned  g_done[BB];                     // last-one-out reset

// ---------------------------------------------------------------------------
// Fused persistent kernel: weight generation + x0 init + all 20 iterations.
// ---------------------------------------------------------------------------
__global__ void __launch_bounds__(512, 2) fused_kernel(
    float* __restrict__ out,
    const float* __restrict__ img,
    const float* __restrict__ feat,
    const float* __restrict__ mask)
{
    extern __shared__ char smem_raw[];
    uint2* ws  = reinterpret_cast<uint2*>(smem_raw);                  // [25][NQ]
    float* xs  = reinterpret_cast<float*>(smem_raw + SMEM_W_BYTES);   // [36][68]
    float* stg = reinterpret_cast<float*>(smem_raw + STG_OFF);        // [3][36][68]

    const int tx = threadIdx.x, ty = threadIdx.y;
    const int tid = ty * 32 + tx;
    const int quad = tid;

    const int b  = blockIdx.z;
    const int h0 = blockIdx.y * TILE_H;
    const int w0 = blockIdx.x * TILE_W;

    const int r0 = 2 * ty;          // local px rows r0, r0+1
    const int c0 = 2 * tx;          // local px cols c0, c0+1
    const size_t p00 = (size_t)(h0 + r0)     * WW + (w0 + c0);
    const size_t p10 = (size_t)(h0 + r0 + 1) * WW + (w0 + c0);

    unsigned* cnt = &g_count[b];

    // ======================= INIT PHASE =======================
    // 1) Stage shifted img tile + halo (3 channels) into smem.
    //    img + 10 BEFORE zero padding (matches reference); OOB = 0 so that
    //    OOB affinities underflow to exactly 0.
    for (int idx = tid; idx < CC * XS_H * XS_W; idx += 512) {
        int c  = idx / (XS_H * XS_W);
        int r  = idx - c * (XS_H * XS_W);
        int ly = r / XS_W, lx = r - ly * XS_W;
        int gh = h0 + ly - 2, gw = w0 + lx - 2;
        bool ok = (gh >= 0) && (gh < HH) && (gw >= 0) && (gw < WW);
        stg[idx] = ok ? img[((size_t)b * CC + c) * HWSZ + gh * WW + gw] + 10.0f
                      : 0.0f;
    }
    __syncthreads();

    // 2) Generate fp16 weights for the 2x2 quad. q_k = half(aff_k); the
    //    normalization is folded into cfac = mask / sum(dequant(q_k)),
    //    which keeps the averaging exact (fp16 error does not compound).
    #define SG(c, ly, lx) stg[(c) * (XS_H * XS_W) + (ly) * XS_W + (lx)]
    float ctr[CC][2][2];
    #pragma unroll
    for (int c = 0; c < CC; c++)
        #pragma unroll
        for (int i = 0; i < 2; i++)
            #pragma unroll
            for (int j = 0; j < 2; j++)
                ctr[c][i][j] = SG(c, r0 + i + 2, c0 + j + 2);

    float qs00 = 0.f, qs01 = 0.f, qs10 = 0.f, qs11 = 0.f;
    uint2 defer[K2 - DEFER_K];

    #pragma unroll
    for (int k = 0; k < K2; k++) {
        const int dy = k / KK, dx = k % KK;
        float w[2][2];
        #pragma unroll
        for (int i = 0; i < 2; i++)
            #pragma unroll
            for (int j = 0; j < 2; j++) {
                float d = 0.f;
                #pragma unroll
                for (int c = 0; c < CC; c++) {
                    float t = SG(c, r0 + i + dy, c0 + j + dx) - ctr[c][i][j];
                    d = fmaf(t, t, d);
                }
                w[i][j] = __expf(-d * INVZ2);
            }
        __half h00 = __float2half_rn(w[0][0]);
        __half h01 = __float2half_rn(w[0][1]);
        __half h10 = __float2half_rn(w[1][0]);
        __half h11 = __float2half_rn(w[1][1]);
        qs00 += __half2float(h00); qs01 += __half2float(h01);
        qs10 += __half2float(h10); qs11 += __half2float(h11);
        __half2 lo = __halves2half2(h00, h01);
        __half2 hi = __halves2half2(h10, h11);
        uint2 val = make_uint2(*reinterpret_cast<unsigned*>(&lo),
                               *reinterpret_cast<unsigned*>(&hi));
        if (k < DEFER_K) ws[k * NQ + quad] = val;   // region [0,81920): safe
        else             defer[k - DEFER_K] = val;
    }
    #undef SG
    __syncthreads();   // all staging reads complete

    // 3) Deferred weight stores (overwrite staging region)
    #pragma unroll
    for (int k = DEFER_K; k < K2; k++)
        ws[k * NQ + quad] = defer[k - DEFER_K];

    // 4) x0 = feat * mask; renorm factors cfac = mask / qs (registers)
    const float2 f0 = *reinterpret_cast<const float2*>(feat + (size_t)b * HWSZ + p00);
    const float2 f1 = *reinterpret_cast<const float2*>(feat + (size_t)b * HWSZ + p10);
    const float2 m0 = *reinterpret_cast<const float2*>(mask + (size_t)b * HWSZ + p00);
    const float2 m1 = *reinterpret_cast<const float2*>(mask + (size_t)b * HWSZ + p10);
    const float2 cf0 = make_float2(m0.x / qs00, m0.y / qs01);
    const float2 cf1 = make_float2(m1.x / qs10, m1.y / qs11);
    const float x00 = f0.x * m0.x, x01 = f0.y * m0.y;
    const float x10 = f1.x * m1.x, x11 = f1.y * m1.y;

    // write x0 interior into xs (overwrites staging tail; staging is dead)
    *reinterpret_cast<float2*>(&xs[(r0 + 2) * XS_W + c0 + 2]) = make_float2(x00, x01);
    *reinterpret_cast<float2*>(&xs[(r0 + 3) * XS_W + c0 + 2]) = make_float2(x10, x11);

    // publish x0 borders to g_x[0] for neighbors' it=0 halo
    const bool b0row = (r0 < 2) || (r0 >= TILE_H - 2);
    const bool b1row = (r0 + 1 < 2) || (r0 + 1 >= TILE_H - 2);
    const bool bcol  = (c0 < 2) || (c0 + 1 >= TILE_W - 2);
    const bool pub0 = b0row || bcol;
    const bool pub1 = b1row || bcol;
    {
        float* dst = &g_x[0][(size_t)b * HWSZ];
        if (pub0) *reinterpret_cast<float2*>(dst + p00) = make_float2(x00, x01);
        if (pub1) *reinterpret_cast<float2*>(dst + p10) = make_float2(x10, x11);
    }
    __threadfence();
    __syncthreads();
    if (tid == 0) {
        atomicAdd(cnt, 1u);
        while (*(volatile unsigned*)cnt < (unsigned)NBLK_B) { }
        __threadfence();
    }
    __syncthreads();

    // ring mapping (tid < 400)
    int rly = -1, rlx = 0;
    if (tid < 136)        { rly = tid / 68;            rlx = tid % 68; }
    else if (tid < 272)   { int t = tid - 136; rly = 34 + t / 68; rlx = t % 68; }
    else if (tid < 336)   { int t = tid - 272; rlx = t & 1;       rly = 2 + (t >> 1); }
    else if (tid < 400)   { int t = tid - 336; rlx = 66 + (t & 1); rly = 2 + (t >> 1); }
    int rgh = 0, rgw = 0; bool rok = false;
    if (rly >= 0) {
        rgh = h0 + rly - 2; rgw = w0 + rlx - 2;
        rok = (rgh >= 0) && (rgh < HH) && (rgw >= 0) && (rgw < WW);
    }

    // ======================= ITERATION LOOP =======================
    for (int it = 0; it < NUM_ITER; it++) {
        // ---- halo ring from global ----
        if (rly >= 0) {
            const float* src = &g_x[it & 1][(size_t)b * HWSZ];
            float v = 0.0f;
            if (rok) v = __ldcg(src + (size_t)rgh * WW + rgw);
            xs[rly * XS_W + rlx] = v;
        }
        __syncthreads();   // sync A

        // ---- compute 2x2 quad ----
        float a00 = 0.f, a01 = 0.f, a10 = 0.f, a11 = 0.f;
        uint2 Wp[5];
        #pragma unroll
        for (int j = 0; j < 6; j++) {
            const float* row = &xs[(r0 + j) * XS_W + c0];
            float2 va = *reinterpret_cast<const float2*>(row);
            float2 vb = *reinterpret_cast<const float2*>(row + 2);
            float2 vc = *reinterpret_cast<const float2*>(row + 4);
            float2 vd = *reinterpret_cast<const float2*>(row + 6);
            float v[7] = { va.x, va.y, vb.x, vb.y, vc.x, vc.y, vd.x };

            uint2 Wc[5];
            if (j < 5) {
                #pragma unroll
                for (int dx = 0; dx < 5; dx++)
                    Wc[dx] = ws[(j * 5 + dx) * NQ + quad];
            }
            #pragma unroll
            for (int dx = 0; dx < 5; dx++) {
                if (j < 5) {
                    float2 fA = __half22float2(*reinterpret_cast<__half2*>(&Wc[dx].x));
                    a00 = fmaf(fA.x, v[dx], a00);
                    a01 = fmaf(fA.y, v[dx + 1], a01);
                }
                if (j >= 1) {
                    float2 fB = __half22float2(*reinterpret_cast<__half2*>(&Wp[dx].y));
                    a10 = fmaf(fB.x, v[dx], a10);
                    a11 = fmaf(fB.y, v[dx + 1], a11);
                }
            }
            if (j < 5) {
                #pragma unroll
                for (int dx = 0; dx < 5; dx++) Wp[dx] = Wc[dx];
            }
        }

        const float o00 = a00 * cf0.x, o01 = a01 * cf0.y;
        const float o10 = a10 * cf1.x, o11 = a11 * cf1.y;

        if (it == NUM_ITER - 1) {
            float* ob = out + (size_t)b * HWSZ;
            *reinterpret_cast<float2*>(ob + p00) = make_float2(o00, o01);
            *reinterpret_cast<float2*>(ob + p10) = make_float2(o10, o11);
            break;
        }

        // publish my 2-wide border (before sync B; fenced per-thread)
        {
            float* dst = &g_x[(it + 1) & 1][(size_t)b * HWSZ];
            if (pub0) *reinterpret_cast<float2*>(dst + p00) = make_float2(o00, o01);
            if (pub1) *reinterpret_cast<float2*>(dst + p10) = make_float2(o10, o11);
        }
        __threadfence();
        __syncthreads();   // sync B: all xs reads done; publishes fenced

        if (tid == 0)
            atomicAdd(cnt, 1u);

        // spin-window overlap: write next-iter interior to smem now
        *reinterpret_cast<float2*>(&xs[(r0 + 2) * XS_W + c0 + 2]) = make_float2(o00, o01);
        *reinterpret_cast<float2*>(&xs[(r0 + 3) * XS_W + c0 + 2]) = make_float2(o10, o11);

        if (tid == 0) {
            const unsigned target = (unsigned)(it + 2) * NBLK_B;
            while (*(volatile unsigned*)cnt < target) { }
            __threadfence();
        }
        __syncthreads();   // sync C
    }

    // ======================= COUNTER RESET (last-one-out) =======================
    __syncthreads();   // whole block finished
    if (tid == 0) {
        unsigned old = atomicAdd(&g_done[b], 1u);
        if (old == (unsigned)(NBLK_B - 1)) {
            // every block in this batch has passed all spins; safe to reset
            atomicExch(&g_count[b], 0u);
            atomicExch(&g_done[b], 0u);
        }
    }
}

// ---------------------------------------------------------------------------
extern "C" void kernel_launch(void* const* d_in, const int* in_sizes, int n_in,
                              void* d_out, int out_size)
{
    const float* img  = (const float*)d_in[0];
    const float* feat = (const float*)d_in[1];
    const float* mask = (const float*)d_in[2];
    float* out = (float*)d_out;

    cudaFuncSetAttribute(fused_kernel,
                         cudaFuncAttributeMaxDynamicSharedMemorySize, SMEM_DYN);

    dim3 blk(32, 16);
    dim3 grd(GRID_X, GRID_Y, BB);        // (6, 12, 4) = 288 blocks
    fused_kernel<<<grd, blk, SMEM_DYN>>>(out, img, feat, mask);
}

// round 15
// speedup vs baseline: 1.0878x; 1.0698x over previous
#include <cuda_runtime.h>
#include <cuda_fp16.h>
#include <cstdint>

// Problem constants
#define BB 4
#define CC 3
#define HH 384
#define WW 384
#define KK 5
#define K2 25
#define HWSZ (HH * WW)          // 147456
#define NUM_ITER 20
#define INVZ2 44.4444444444444444f   // 1 / 0.15^2

// ---------------- persistent kernel geometry ----------------
#define TILE_W 64
#define TILE_H 32
#define XS_W (TILE_W + 4)    // 68
#define XS_H (TILE_H + 4)    // 36
#define NQ 512
#define GRID_X (WW / TILE_W) // 6
#define GRID_Y (HH / TILE_H) // 12
#define NBLK_B (GRID_X * GRID_Y)     // 72 blocks per batch

// 24 stored weight planes (center tap k=12 is exp(0)=1, held as a constant)
#define NWP 24
// SMEM layout:
//  [0, 98304)         ws: fp16 weights, uint2 [24][NQ]
//  [98304, 108096)    xs: x tile [36][68] fp32
//  [108096, 108112)   pad (vd float2 tail overread)
//  Staging (init only): img 3ch tile = 29376 B at [78736, 108112).
//  Weight planes idx 0..18 ([0,77824)) are disjoint from staging; planes
//  19..23 are deferred to registers and stored after the staging-read sync.
#define SMEM_W_BYTES (NWP * NQ * 8)                      // 98304
#define SMEM_X_BYTES (XS_H * XS_W * 4)                   // 9792
#define SMEM_DYN (SMEM_W_BYTES + SMEM_X_BYTES + 16)      // 108112
#define STG_BYTES (CC * XS_H * XS_W * 4)                 // 29376
#define STG_OFF (SMEM_DYN - STG_BYTES)                   // 78736 (16B aligned)
#define DEFER_IDX 19                                     // planes >= 19 deferred

// Scratch (global):
__device__ float     g_x[2][(size_t)BB * HWSZ];      // ping-pong border exchange
__device__ unsigned  g_count[BB];                    // per-batch barrier counters
__device__ unsigned  g_done[BB];                     // last-one-out reset

// arrival: release-reduction (no warp-stalling membar; ordering via L2 queue;
// other threads' prior stores are ordered in by the preceding bar.sync)
__device__ __forceinline__ void red_release_add(unsigned* p, unsigned v) {
    asm volatile("red.release.gpu.global.add.u32 [%0], %1;"
                 :: "l"(p), "r"(v) : "memory");
}

// ---------------------------------------------------------------------------
// Fused persistent kernel: weight generation + x0 init + all 20 iterations.
// ---------------------------------------------------------------------------
__global__ void __launch_bounds__(512, 2) fused_kernel(
    float* __restrict__ out,
    const float* __restrict__ img,
    const float* __restrict__ feat,
    const float* __restrict__ mask)
{
    extern __shared__ char smem_raw[];
    uint2* ws  = reinterpret_cast<uint2*>(smem_raw);                  // [24][NQ]
    float* xs  = reinterpret_cast<float*>(smem_raw + SMEM_W_BYTES);   // [36][68]
    float* stg = reinterpret_cast<float*>(smem_raw + STG_OFF);        // [3][36][68]

    const int tx = threadIdx.x, ty = threadIdx.y;
    const int tid = ty * 32 + tx;
    const int quad = tid;

    const int b  = blockIdx.z;
    const int h0 = blockIdx.y * TILE_H;
    const int w0 = blockIdx.x * TILE_W;

    const int r0 = 2 * ty;
    const int c0 = 2 * tx;
    const size_t p00 = (size_t)(h0 + r0)     * WW + (w0 + c0);
    const size_t p10 = (size_t)(h0 + r0 + 1) * WW + (w0 + c0);

    unsigned* cnt = &g_count[b];

    // ======================= INIT PHASE =======================
    // Stage shifted img tile + halo (img + 10 BEFORE zero padding; OOB = 0
    // so OOB affinities underflow to exactly 0 — matches reference).
    for (int idx = tid; idx < CC * XS_H * XS_W; idx += 512) {
        int c  = idx / (XS_H * XS_W);
        int r  = idx - c * (XS_H * XS_W);
        int ly = r / XS_W, lx = r - ly * XS_W;
        int gh = h0 + ly - 2, gw = w0 + lx - 2;
        bool ok = (gh >= 0) && (gh < HH) && (gw >= 0) && (gw < WW);
        stg[idx] = ok ? img[((size_t)b * CC + c) * HWSZ + gh * WW + gw] + 10.0f
                      : 0.0f;
    }
    __syncthreads();

    // Generate fp16 weights (q_k = half(aff_k); normalization folded into
    // cfac = mask / sum(dequant(q_k)) -> exact averaging, no error compound).
    // Center tap (k=12): aff = exp(0) = 1 exactly; not stored.
    #define SG(c, ly, lx) stg[(c) * (XS_H * XS_W) + (ly) * XS_W + (lx)]
    float ctr[CC][2][2];
    #pragma unroll
    for (int c = 0; c < CC; c++)
        #pragma unroll
        for (int i = 0; i < 2; i++)
            #pragma unroll
            for (int j = 0; j < 2; j++)
                ctr[c][i][j] = SG(c, r0 + i + 2, c0 + j + 2);

    float qs00 = 1.f, qs01 = 1.f, qs10 = 1.f, qs11 = 1.f;   // center included
    uint2 defer[NWP - DEFER_IDX];

    #pragma unroll
    for (int k = 0; k < K2; k++) {
        if (k == 12) continue;                       // center: implicit 1.0
        const int widx = (k < 12) ? k : k - 1;       // stored plane index
        const int dy = k / KK, dx = k % KK;
        float w[2][2];
        #pragma unroll
        for (int i = 0; i < 2; i++)
            #pragma unroll
            for (int j = 0; j < 2; j++) {
                float d = 0.f;
                #pragma unroll
                for (int c = 0; c < CC; c++) {
                    float t = SG(c, r0 + i + dy, c0 + j + dx) - ctr[c][i][j];
                    d = fmaf(t, t, d);
                }
                w[i][j] = __expf(-d * INVZ2);
            }
        __half h00 = __float2half_rn(w[0][0]);
        __half h01 = __float2half_rn(w[0][1]);
        __half h10 = __float2half_rn(w[1][0]);
        __half h11 = __float2half_rn(w[1][1]);
        qs00 += __half2float(h00); qs01 += __half2float(h01);
        qs10 += __half2float(h10); qs11 += __half2float(h11);
        __half2 lo = __halves2half2(h00, h01);
        __half2 hi = __halves2half2(h10, h11);
        uint2 val = make_uint2(*reinterpret_cast<unsigned*>(&lo),
                               *reinterpret_cast<unsigned*>(&hi));
        if (widx < DEFER_IDX) ws[widx * NQ + quad] = val;
        else                  defer[widx - DEFER_IDX] = val;
    }
    #undef SG
    __syncthreads();   // all staging reads complete

    #pragma unroll
    for (int widx = DEFER_IDX; widx < NWP; widx++)
        ws[widx * NQ + quad] = defer[widx - DEFER_IDX];

    // x0 = feat * mask; renorm factors cfac = mask / qs (registers)
    const float2 f0 = *reinterpret_cast<const float2*>(feat + (size_t)b * HWSZ + p00);
    const float2 f1 = *reinterpret_cast<const float2*>(feat + (size_t)b * HWSZ + p10);
    const float2 m0 = *reinterpret_cast<const float2*>(mask + (size_t)b * HWSZ + p00);
    const float2 m1 = *reinterpret_cast<const float2*>(mask + (size_t)b * HWSZ + p10);
    const float2 cf0 = make_float2(m0.x / qs00, m0.y / qs01);
    const float2 cf1 = make_float2(m1.x / qs10, m1.y / qs11);
    const float x00 = f0.x * m0.x, x01 = f0.y * m0.y;
    const float x10 = f1.x * m1.x, x11 = f1.y * m1.y;

    *reinterpret_cast<float2*>(&xs[(r0 + 2) * XS_W + c0 + 2]) = make_float2(x00, x01);
    *reinterpret_cast<float2*>(&xs[(r0 + 3) * XS_W + c0 + 2]) = make_float2(x10, x11);

    const bool b0row = (r0 < 2) || (r0 >= TILE_H - 2);
    const bool b1row = (r0 + 1 < 2) || (r0 + 1 >= TILE_H - 2);
    const bool bcol  = (c0 < 2) || (c0 + 1 >= TILE_W - 2);
    const bool pub0 = b0row || bcol;
    const bool pub1 = b1row || bcol;
    {
        float* dst = &g_x[0][(size_t)b * HWSZ];
        if (pub0) *reinterpret_cast<float2*>(dst + p00) = make_float2(x00, x01);
        if (pub1) *reinterpret_cast<float2*>(dst + p10) = make_float2(x10, x11);
    }
    __syncthreads();                       // all publishes ordered before release
    if (tid == 0) {
        red_release_add(cnt, 1u);
        while (*(volatile unsigned*)cnt < (unsigned)NBLK_B) { }
        __threadfence();
    }
    __syncthreads();

    // ring mapping (tid < 400)
    int rly = -1, rlx = 0;
    if (tid < 136)        { rly = tid / 68;            rlx = tid % 68; }
    else if (tid < 272)   { int t = tid - 136; rly = 34 + t / 68; rlx = t % 68; }
    else if (tid < 336)   { int t = tid - 272; rlx = t & 1;       rly = 2 + (t >> 1); }
    else if (tid < 400)   { int t = tid - 336; rlx = 66 + (t & 1); rly = 2 + (t >> 1); }
    int rgh = 0, rgw = 0; bool rok = false;
    if (rly >= 0) {
        rgh = h0 + rly - 2; rgw = w0 + rlx - 2;
        rok = (rgh >= 0) && (rgh < HH) && (rgw >= 0) && (rgw < WW);
    }

    // half2(1,1) for the center tap slot
    const uint2 ONE2 = make_uint2(0x3C003C00u, 0x3C003C00u);

    // ======================= ITERATION LOOP =======================
    for (int it = 0; it < NUM_ITER; it++) {
        // ---- halo ring from global ----
        if (rly >= 0) {
            const float* src = &g_x[it & 1][(size_t)b * HWSZ];
            float v = 0.0f;
            if (rok) v = __ldcg(src + (size_t)rgh * WW + rgw);
            xs[rly * XS_W + rlx] = v;
        }
        __syncthreads();   // sync A

        // ---- compute 2x2 quad ----
        float a00 = 0.f, a01 = 0.f, a10 = 0.f, a11 = 0.f;
        uint2 Wp[5];
        #pragma unroll
        for (int j = 0; j < 6; j++) {
            const float* row = &xs[(r0 + j) * XS_W + c0];
            float2 va = *reinterpret_cast<const float2*>(row);
            float2 vb = *reinterpret_cast<const float2*>(row + 2);
            float2 vc = *reinterpret_cast<const float2*>(row + 4);
            float2 vd = *reinterpret_cast<const float2*>(row + 6);
            float v[7] = { va.x, va.y, vb.x, vb.y, vc.x, vc.y, vd.x };

            uint2 Wc[5];
            if (j < 5) {
                #pragma unroll
                for (int dx = 0; dx < 5; dx++) {
                    const int k = j * 5 + dx;
                    if (k == 12) Wc[dx] = ONE2;                      // center
                    else {
                        const int widx = (k < 12) ? k : k - 1;
                        Wc[dx] = ws[widx * NQ + quad];
                    }
                }
            }
            #pragma unroll
            for (int dx = 0; dx < 5; dx++) {
                if (j < 5) {
                    float2 fA = __half22float2(*reinterpret_cast<__half2*>(&Wc[dx].x));
                    a00 = fmaf(fA.x, v[dx], a00);
                    a01 = fmaf(fA.y, v[dx + 1], a01);
                }
                if (j >= 1) {
                    float2 fB = __half22float2(*reinterpret_cast<__half2*>(&Wp[dx].y));
                    a10 = fmaf(fB.x, v[dx], a10);
                    a11 = fmaf(fB.y, v[dx + 1], a11);
                }
            }
            if (j < 5) {
                #pragma unroll
                for (int dx = 0; dx < 5; dx++) Wp[dx] = Wc[dx];
            }
        }

        const float o00 = a00 * cf0.x, o01 = a01 * cf0.y;
        const float o10 = a10 * cf1.x, o11 = a11 * cf1.y;

        if (it == NUM_ITER - 1) {
            float* ob = out + (size_t)b * HWSZ;
            *reinterpret_cast<float2*>(ob + p00) = make_float2(o00, o01);
            *reinterpret_cast<float2*>(ob + p10) = make_float2(o10, o11);
            break;
        }

        // publish my 2-wide border
        {
            float* dst = &g_x[(it + 1) & 1][(size_t)b * HWSZ];
            if (pub0) *reinterpret_cast<float2*>(dst + p00) = make_float2(o00, o01);
            if (pub1) *reinterpret_cast<float2*>(dst + p10) = make_float2(o10, o11);
        }
        __syncthreads();   // sync B: xs reads done; publishes ordered before release

        if (tid == 0)
            red_release_add(cnt, 1u);     // no membar: release-reduction

        // spin-window overlap: write next-iter interior to smem now
        *reinterpret_cast<float2*>(&xs[(r0 + 2) * XS_W + c0 + 2]) = make_float2(o00, o01);
        *reinterpret_cast<float2*>(&xs[(r0 + 3) * XS_W + c0 + 2]) = make_float2(o10, o11);

        if (tid == 0) {
            const unsigned target = (unsigned)(it + 2) * NBLK_B;
            while (*(volatile unsigned*)cnt < target) { }
            __threadfence();
        }
        __syncthreads();   // sync C
    }

    // ======================= COUNTER RESET (last-one-out) =======================
    __syncthreads();
    if (tid == 0) {
        unsigned old = atomicAdd(&g_done[b], 1u);
        if (old == (unsigned)(NBLK_B - 1)) {
            atomicExch(&g_count[b], 0u);
            atomicExch(&g_done[b], 0u);
        }
    }
}

// ---------------------------------------------------------------------------
extern "C" void kernel_launch(void* const* d_in, const int* in_sizes, int n_in,
                              void* d_out, int out_size)
{
    const float* img  = (const float*)d_in[0];
    const float* feat = (const float*)d_in[1];
    const float* mask = (const float*)d_in[2];
    float* out = (float*)d_out;

    cudaFuncSetAttribute(fused_kernel,
                         cudaFuncAttributeMaxDynamicSharedMemorySize, SMEM_DYN);

    dim3 blk(32, 16);
    dim3 grd(GRID_X, GRID_Y, BB);        // (6, 12, 4) = 288 blocks
    fused_kernel<<<grd, blk, SMEM_DYN>>>(out, img, feat, mask);
}